// round 1
// baseline (speedup 1.0000x reference)
#include <cuda_runtime.h>

#define B_   64
#define LX_  512
#define LY_  512
#define DIM_ 64
#define BIGF 1e30f

// Diagonal-major scratch: g_Dt[b][t][i] = D[b][i][t - i], t in [0, 1023)
// 64 * 1024 * 512 floats = 128 MiB static device scratch (allowed).
__device__ float g_Dt[(size_t)B_ * 1024 * 512];

// ---------------------------------------------------------------------------
// Kernel 1: batched pairwise squared-L2 "GEMM", 64x64 tiles, 256 threads,
// 4x4 register micro-tiles, k-major smem operands, diagonal-major writeout.
// ---------------------------------------------------------------------------
__global__ __launch_bounds__(256) void sdtw_gemm_kernel(
    const float* __restrict__ X, const float* __restrict__ Y)
{
    __shared__ float Xs[DIM_][68];   // k-major: Xs[k][i_local]
    __shared__ float Ys[DIM_][68];   // k-major: Ys[k][j_local]
    __shared__ float sx2[64];
    __shared__ float sy2[64];

    const int b  = blockIdx.z;
    const int i0 = blockIdx.y * 64;
    const int j0 = blockIdx.x * 64;
    const int tid = threadIdx.x;

    const float* Xb = X + ((size_t)b * LX_ + i0) * DIM_;
    const float* Yb = Y + ((size_t)b * LY_ + j0) * DIM_;

    // Load 64x64 X tile and 64x64 Y tile, transposing to k-major in smem.
#pragma unroll
    for (int it = 0; it < 4; ++it) {
        int linear = it * 256 + tid;      // 0..1023
        int row = linear >> 4;            // 0..63 (i or j local)
        int k4  = (linear & 15) << 2;     // 0..60
        float4 xv = *(const float4*)(Xb + row * DIM_ + k4);
        Xs[k4 + 0][row] = xv.x; Xs[k4 + 1][row] = xv.y;
        Xs[k4 + 2][row] = xv.z; Xs[k4 + 3][row] = xv.w;
        float4 yv = *(const float4*)(Yb + row * DIM_ + k4);
        Ys[k4 + 0][row] = yv.x; Ys[k4 + 1][row] = yv.y;
        Ys[k4 + 2][row] = yv.z; Ys[k4 + 3][row] = yv.w;
    }
    __syncthreads();

    // Row norms from smem (column reads -> conflict-free).
    if (tid < 64) {
        float v = 0.f;
#pragma unroll 8
        for (int k = 0; k < DIM_; ++k) v = fmaf(Xs[k][tid], Xs[k][tid], v);
        sx2[tid] = v;
    } else if (tid < 128) {
        int j = tid - 64;
        float v = 0.f;
#pragma unroll 8
        for (int k = 0; k < DIM_; ++k) v = fmaf(Ys[k][j], Ys[k][j], v);
        sy2[j] = v;
    }
    __syncthreads();

    const int tx = tid & 15;   // j dimension
    const int ty = tid >> 4;   // i dimension

    float acc[4][4];
#pragma unroll
    for (int r = 0; r < 4; ++r)
#pragma unroll
        for (int c = 0; c < 4; ++c) acc[r][c] = 0.f;

#pragma unroll 8
    for (int k = 0; k < DIM_; ++k) {
        float4 xv = *(const float4*)&Xs[k][ty * 4];
        float4 yv = *(const float4*)&Ys[k][tx * 4];
        float xr[4] = {xv.x, xv.y, xv.z, xv.w};
        float yc[4] = {yv.x, yv.y, yv.z, yv.w};
#pragma unroll
        for (int r = 0; r < 4; ++r)
#pragma unroll
            for (int c = 0; c < 4; ++c)
                acc[r][c] = fmaf(xr[r], yc[c], acc[r][c]);
    }

    // d = x2 + y2 - 2*dot (same formula as the reference).
    float dres[4][4];
#pragma unroll
    for (int r = 0; r < 4; ++r) {
        float xr2 = sx2[ty * 4 + r];
#pragma unroll
        for (int c = 0; c < 4; ++c)
            dres[r][c] = xr2 + sy2[tx * 4 + c] - 2.0f * acc[r][c];
    }

    __syncthreads();  // everyone done reading Xs/Ys; safe to alias as stage

    // Stage tile: Cs[i_local][j_local], pitch 66 so anti-diagonal stride = 65
    // (odd -> bank-conflict-free). Cs needs 64*66 = 4224 floats; Xs has 4352.
    float* Cs = &Xs[0][0];
    const int CP = 66;
#pragma unroll
    for (int r = 0; r < 4; ++r)
#pragma unroll
        for (int c = 0; c < 4; ++c)
            Cs[(ty * 4 + r) * CP + (tx * 4 + c)] = dres[r][c];
    __syncthreads();

    // Writeout along anti-diagonals: Dt[b][i0+j0+tl][i0+li].
    // Lanes cover i (coalesced STG), loop covers the 127 tile diagonals.
    float* Dtb = g_Dt + (size_t)b * (1024 * 512) + (size_t)(i0 + j0) * 512 + i0;
    const int g  = tid >> 6;   // 0..3
    const int li = tid & 63;   // 0..63
    for (int tl = g; tl < 127; tl += 4) {
        int ilo = tl - 63; if (ilo < 0) ilo = 0;
        int ihi = tl;      if (ihi > 63) ihi = 63;
        if (li >= ilo && li <= ihi) {
            // Cs[li][tl - li] : addr = li*66 + tl - li = li*65 + tl
            Dtb[(size_t)tl * 512 + li] = Cs[li * (CP - 1) + tl];
        }
    }
}

// ---------------------------------------------------------------------------
// Kernel 2: soft-DTW anti-diagonal wavefront. One CTA per batch,
// one thread per row i. Double-buffered float2(r1, r2) ring in smem with a
// BIG sentinel at index 0; one LDS.64 + one STS.64 + one coalesced
// prefetched LDG per thread per step; one __syncthreads per diagonal.
// ---------------------------------------------------------------------------
__global__ __launch_bounds__(512) void sdtw_dp_kernel(float* __restrict__ out)
{
    __shared__ float2 rbuf[2][LX_ + 1];

    const int i = threadIdx.x;
    const int b = blockIdx.x;
    const float* __restrict__ Db = g_Dt + (size_t)b * (1024 * 512);

    rbuf[0][i + 1] = make_float2(BIGF, BIGF);
    rbuf[1][i + 1] = make_float2(BIGF, BIGF);
    if (i == 0) {
        rbuf[0][0] = make_float2(BIGF, BIGF);
        rbuf[1][0] = make_float2(BIGF, BIGF);
    }

    float rp1 = BIGF;             // my r1[i] (previous diagonal's value)
    float d0 = Db[i];             // D for step t   (garbage where invalid: ok)
    float d1 = Db[512 + i];       // D for step t+1
    __syncthreads();

#pragma unroll 1
    for (int t = 0; t < LX_ + LY_ - 1; ++t) {
        float dcur = d0;
        d0 = d1;
        int tp = t + 2; if (tp > LX_ + LY_ - 2) tp = LX_ + LY_ - 2;
        d1 = __ldg(Db + (size_t)tp * 512 + i);   // prefetch 2 steps ahead

        // neighbor (i-1): .x = r1[i-1], .y = r2[i-1]; index 0 is BIG sentinel
        float2 nb = rbuf[(t + 1) & 1][i];
        float up = nb.x;
        float dg = nb.y;
        if (i == 0 && t == 0) dg = 0.0f;         // soft-DTW origin

        int j = t - i;
        float lf = (j >= 1) ? rp1 : BIGF;

        float m = fminf(dg, fminf(up, lf));
        float s = __expf(m - dg) + __expf(m - up) + __expf(m - lf);
        float smin = m - __logf(s);              // gamma = 1

        float rc = ((unsigned)j < (unsigned)LY_) ? (dcur + smin) : BIGF;

        rbuf[t & 1][i + 1] = make_float2(rc, rp1);
        rp1 = rc;
        __syncthreads();
    }

    if (i == LX_ - 1) out[b] = rp1;   // R[LX-1][LY-1]
}

// ---------------------------------------------------------------------------
extern "C" void kernel_launch(void* const* d_in, const int* in_sizes, int n_in,
                              void* d_out, int out_size)
{
    (void)in_sizes; (void)n_in; (void)out_size;
    const float* X = (const float*)d_in[0];
    const float* Y = (const float*)d_in[1];
    float* out = (float*)d_out;

    dim3 gg(LY_ / 64, LX_ / 64, B_);   // (8, 8, 64) tiles
    sdtw_gemm_kernel<<<gg, 256>>>(X, Y);
    sdtw_dp_kernel<<<B_, LX_>>>(out);
}